// round 5
// baseline (speedup 1.0000x reference)
#include <cuda_runtime.h>
#include <cstdint>

// -------------------- problem constants --------------------
#define B_SZ 4096
#define I_SZ 1024
#define H_SZ 2048
#define NSTEPS 5
#define DT_C 0.1f

// -------------------- GEMM tiling --------------------
#define BM 128
#define BN 128
#define BK 32            // two 16-float sub-tiles per stage
#define NSTAGE 3
#define THREADS 256

#define SUB_A   8192                    // 128 rows x 64B
#define SUB_B   8192
#define SUB_BYTES (3 * 8192)            // A + B0 + B1 = 24576
#define STAGE_BYTES (2 * SUB_BYTES)     // two k-subs = 49152
#define SMEM_TOTAL (NSTAGE * STAGE_BYTES)  // 147456

// -------------------- scratch --------------------
__device__ float g_C1[B_SZ * H_SZ];
__device__ float g_C2[B_SZ * H_SZ];
__device__ float g_hA[B_SZ * H_SZ];
__device__ float g_hB[B_SZ * H_SZ];

// -------------------- PTX helpers --------------------
__device__ __forceinline__ void cp16(uint32_t smem, const void* g) {
    asm volatile("cp.async.cg.shared.global [%0], [%1], 16;" :: "r"(smem), "l"(g) : "memory");
}
__device__ __forceinline__ void cp_commit() {
    asm volatile("cp.async.commit_group;" ::: "memory");
}
template <int N>
__device__ __forceinline__ void cp_wait() {
    asm volatile("cp.async.wait_group %0;" :: "n"(N) : "memory");
}
__device__ __forceinline__ void ldsm4(uint32_t* r, uint32_t a) {
    asm volatile("ldmatrix.sync.aligned.m8n8.x4.shared.b16 {%0,%1,%2,%3}, [%4];"
                 : "=r"(r[0]), "=r"(r[1]), "=r"(r[2]), "=r"(r[3]) : "r"(a));
}
__device__ __forceinline__ void mma_tf32(float* d, const uint32_t* a, const uint32_t* b) {
    asm volatile(
        "mma.sync.aligned.m16n8k8.row.col.f32.tf32.tf32.f32 "
        "{%0,%1,%2,%3}, {%4,%5,%6,%7}, {%8,%9}, {%0,%1,%2,%3};"
        : "+f"(d[0]), "+f"(d[1]), "+f"(d[2]), "+f"(d[3])
        : "r"(a[0]), "r"(a[1]), "r"(a[2]), "r"(a[3]), "r"(b[0]), "r"(b[1]));
}

// swizzled smem byte address within an 8K sub-block (64B rows, 4x16B chunks)
__device__ __forceinline__ uint32_t swadr(uint32_t base, int r, int g) {
    const int c = g ^ (r & 3) ^ ((r >> 2) & 1);
    return base + (uint32_t)(r * 64 + c * 16);
}

// -------------------- fused dual-B tf32 GEMM --------------------
// acc0 = A @ B0^T, acc1 = A @ B1^T over tile (m0:+128, n0:+128).
// LIQ=0: o0 = acc0 + e0[col], o1 = acc1 + e1[col]   (bias epilogue)
// LIQ=1: liquid step epilogue: g1=acc0 (tau path), g2=acc1 (rec path)
//        e0=C1, e1=C2, e2=h_in, e3=tau_base; o0=h_out, o1=tau_out(optional)
template <int LIQ>
__global__ void __launch_bounds__(THREADS, 1)
gemm2_tf32(const float* __restrict__ A, int lda,
           const float* __restrict__ B0, int ldb0,
           const float* __restrict__ B1, int ldb1,
           int K,
           float* __restrict__ o0, float* __restrict__ o1,
           const float* __restrict__ e0, const float* __restrict__ e1,
           const float* __restrict__ e2, const float* __restrict__ e3)
{
    extern __shared__ __align__(1024) char smem[];
    const uint32_t sb = (uint32_t)__cvta_generic_to_shared(smem);

    const int tid  = threadIdx.x;
    const int lane = tid & 31;
    const int wid  = tid >> 5;
    const int wm   = (wid >> 2) * 64;   // 0 / 64
    const int wn   = (wid & 3) * 32;    // 0..96

    const int m0 = blockIdx.y * BM;
    const int n0 = blockIdx.x * BN;

    // ---- loader coordinates: row lr (0..127), two 16B chunks ----
    const int lr  = tid >> 1;
    const int lg0 = (tid & 1) * 2;
    const int lg1 = lg0 + 1;
    const float* gA  = A  + (long)(m0 + lr) * lda;
    const float* gB0 = B0 + (long)(n0 + lr) * ldb0;
    const float* gB1 = B1 + (long)(n0 + lr) * ldb1;

    // ---- ldmatrix lane coordinates ----
    const int arow = (lane & 7) + ((lane >> 3) & 1) * 8;
    const int agof = (lane >> 4);
    const int brow = (lane & 7) + ((lane >> 4) & 1) * 8;
    const int bgof = (lane >> 3) & 1;

    float acc0[4][4][4], acc1[4][4][4];
#pragma unroll
    for (int mt = 0; mt < 4; mt++)
#pragma unroll
        for (int nt = 0; nt < 4; nt++)
#pragma unroll
            for (int r = 0; r < 4; r++) { acc0[mt][nt][r] = 0.f; acc1[mt][nt][r] = 0.f; }

    const int nK = K / BK;

    // ---- stage loader: 12 cp16/thread ----
    auto load_stage = [&](int s, int kt) {
        const uint32_t st = sb + s * STAGE_BYTES;
#pragma unroll
        for (int sub = 0; sub < 2; sub++) {
            const uint32_t sA  = st + sub * SUB_BYTES;
            const uint32_t sB0 = sA + SUB_A;
            const uint32_t sB1 = sB0 + SUB_B;
            const int koff = kt * BK + sub * 16;
            cp16(swadr(sA,  lr, lg0), gA  + koff + lg0 * 4);
            cp16(swadr(sA,  lr, lg1), gA  + koff + lg1 * 4);
            cp16(swadr(sB0, lr, lg0), gB0 + koff + lg0 * 4);
            cp16(swadr(sB0, lr, lg1), gB0 + koff + lg1 * 4);
            cp16(swadr(sB1, lr, lg0), gB1 + koff + lg0 * 4);
            cp16(swadr(sB1, lr, lg1), gB1 + koff + lg1 * 4);
        }
    };

    // prologue
#pragma unroll
    for (int s = 0; s < NSTAGE - 1; s++) {
        load_stage(s, s);
        cp_commit();
    }

    for (int kt = 0; kt < nK; kt++) {
        cp_wait<NSTAGE - 2>();
        __syncthreads();

        const int kload = kt + NSTAGE - 1;
        if (kload < nK) load_stage(kload % NSTAGE, kload);
        cp_commit();

        const uint32_t st = sb + (kt % NSTAGE) * STAGE_BYTES;

#pragma unroll
        for (int ks = 0; ks < 4; ks++) {
            const uint32_t sA  = st + (ks >> 1) * SUB_BYTES;
            const uint32_t sB0 = sA + SUB_A;
            const uint32_t sB1 = sB0 + SUB_B;
            const int kq = ks & 1;

            uint32_t af[4][4], b0f[2][4], b1f[2][4];
#pragma unroll
            for (int mt = 0; mt < 4; mt++)
                ldsm4(af[mt], swadr(sA, wm + mt * 16 + arow, 2 * kq + agof));
#pragma unroll
            for (int p = 0; p < 2; p++) {
                ldsm4(b0f[p], swadr(sB0, wn + p * 16 + brow, 2 * kq + bgof));
                ldsm4(b1f[p], swadr(sB1, wn + p * 16 + brow, 2 * kq + bgof));
            }
#pragma unroll
            for (int mt = 0; mt < 4; mt++)
#pragma unroll
                for (int p = 0; p < 2; p++) {
                    mma_tf32(acc0[mt][2 * p],     af[mt], &b0f[p][0]);
                    mma_tf32(acc1[mt][2 * p],     af[mt], &b1f[p][0]);
                    mma_tf32(acc0[mt][2 * p + 1], af[mt], &b0f[p][2]);
                    mma_tf32(acc1[mt][2 * p + 1], af[mt], &b1f[p][2]);
                }
        }
    }

    // ---- epilogue ----
    const int grp = lane >> 2;
    const int tig = lane & 3;

#pragma unroll
    for (int mt = 0; mt < 4; mt++) {
        const int row0 = m0 + wm + mt * 16 + grp;
#pragma unroll
        for (int nt = 0; nt < 4; nt++) {
            const int col = n0 + wn + nt * 8 + 2 * tig;
            if (LIQ == 0) {
                const float b0 = __ldg(e0 + col), b0b = __ldg(e0 + col + 1);
                const float b1 = __ldg(e1 + col), b1b = __ldg(e1 + col + 1);
                float2 u0, u1, v0, v1;
                u0.x = acc0[mt][nt][0] + b0;  u0.y = acc0[mt][nt][1] + b0b;
                u1.x = acc0[mt][nt][2] + b0;  u1.y = acc0[mt][nt][3] + b0b;
                v0.x = acc1[mt][nt][0] + b1;  v0.y = acc1[mt][nt][1] + b1b;
                v1.x = acc1[mt][nt][2] + b1;  v1.y = acc1[mt][nt][3] + b1b;
                *(float2*)(o0 + (long)row0 * H_SZ + col)       = u0;
                *(float2*)(o0 + (long)(row0 + 8) * H_SZ + col) = u1;
                *(float2*)(o1 + (long)row0 * H_SZ + col)       = v0;
                *(float2*)(o1 + (long)(row0 + 8) * H_SZ + col) = v1;
            } else {
                const float2 tb = *(const float2*)(e3 + col);
#pragma unroll
                for (int rr = 0; rr < 2; rr++) {
                    const long off = (long)(row0 + rr * 8) * H_SZ + col;
                    const float2 c1v = *(const float2*)(e0 + off);
                    const float2 c2v = *(const float2*)(e1 + off);
                    const float2 hv  = *(const float2*)(e2 + off);
                    float2 hn, tv;
                    {
                        const float g1 = acc0[mt][nt][2 * rr];
                        const float g2 = acc1[mt][nt][2 * rr];
                        const float tl = c2v.x + g1;
                        const float sg = 1.f / (1.f + __expf(-tl));
                        const float tau = tb.x * (0.5f + sg);
                        const float act = tanhf(g2 + c1v.x);
                        hn.x = hv.x + DT_C * (act - hv.x) / tau;
                        tv.x = tau;
                    }
                    {
                        const float g1 = acc0[mt][nt][2 * rr + 1];
                        const float g2 = acc1[mt][nt][2 * rr + 1];
                        const float tl = c2v.y + g1;
                        const float sg = 1.f / (1.f + __expf(-tl));
                        const float tau = tb.y * (0.5f + sg);
                        const float act = tanhf(g2 + c1v.y);
                        hn.y = hv.y + DT_C * (act - hv.y) / tau;
                        tv.y = tau;
                    }
                    *(float2*)(o0 + off) = hn;
                    if (o1) *(float2*)(o1 + off) = tv;
                }
            }
        }
    }
}

// -------------------- launcher --------------------
extern "C" void kernel_launch(void* const* d_in, const int* in_sizes, int n_in,
                              void* d_out, int out_size)
{
    (void)in_sizes; (void)n_in; (void)out_size;

    const float* x           = (const float*)d_in[0];
    const float* hidden      = (const float*)d_in[1];
    const float* W_rec       = (const float*)d_in[2];
    const float* W_in_w      = (const float*)d_in[3];
    const float* W_in_b      = (const float*)d_in[4];
    const float* tau_base    = (const float*)d_in[5];
    const float* tau_adapt_w = (const float*)d_in[6];
    const float* tau_adapt_b = (const float*)d_in[7];

    float* out_h   = (float*)d_out;
    float* out_tau = out_h + (long)B_SZ * H_SZ;

    float *C1, *C2, *hA, *hB;
    cudaGetSymbolAddress((void**)&C1, g_C1);
    cudaGetSymbolAddress((void**)&C2, g_C2);
    cudaGetSymbolAddress((void**)&hA, g_hA);
    cudaGetSymbolAddress((void**)&hB, g_hB);

    cudaFuncSetAttribute(gemm2_tf32<0>, cudaFuncAttributeMaxDynamicSharedMemorySize, SMEM_TOTAL);
    cudaFuncSetAttribute(gemm2_tf32<1>, cudaFuncAttributeMaxDynamicSharedMemorySize, SMEM_TOTAL);

    const int ldtau = I_SZ + H_SZ;     // 3072
    dim3 gg(H_SZ / BN, B_SZ / BM);     // (16, 32) = 512 CTAs

    // invariants: C1 = x@W_in^T + W_in_b ; C2 = x@tau_x^T + tau_adapt_b
    gemm2_tf32<0><<<gg, THREADS, SMEM_TOTAL>>>(
        x, I_SZ,
        W_in_w, I_SZ,
        tau_adapt_w, ldtau,
        I_SZ,
        C1, C2, W_in_b, tau_adapt_b, nullptr, nullptr);

    // 5 fused steps: G1 = h@tau_h^T (acc0), G2 = h@W_rec^T (acc1), liquid epilogue
    const float* h = hidden;
    float* bufs[2] = {hA, hB};
    for (int s = 0; s < NSTEPS; s++) {
        float* ho = (s == NSTEPS - 1) ? out_h   : bufs[s & 1];
        float* to = (s == NSTEPS - 1) ? out_tau : nullptr;
        gemm2_tf32<1><<<gg, THREADS, SMEM_TOTAL>>>(
            h, H_SZ,
            tau_adapt_w + I_SZ, ldtau,
            W_rec, H_SZ,
            H_SZ,
            ho, to, C1, C2, h, tau_base);
        h = ho;
    }
}